// round 1
// baseline (speedup 1.0000x reference)
#include <cuda_runtime.h>
#include <cuda_bf16.h>
#include <math.h>

// Problem constants
#define BATCH   2
#define NPTS    2048
#define HEADS   8
#define DHEAD   64
#define KNB     32
#define DIMF    512
#define INNER   512          // HEADS*DHEAD
#define QKVN    1536         // 3*INNER
#define ROWS    (BATCH*NPTS) // 4096
#define FEAT_OUT (ROWS*DIMF) // 2097152

// Scratch (device globals: allocation-free per harness rules)
__device__ float g_qkv[ROWS * QKVN];   // 25.2 MB
__device__ float g_att[ROWS * INNER];  // 8.4 MB

// ---------------------------------------------------------------------------
// Register-blocked fp32 SGEMM: C[M,N] = A[M,K] @ B[K,N] (+ bias[N])
// Requires M%128==0, N%128==0, K%16==0 (holds: 4096, 1536/512, 512)
// ---------------------------------------------------------------------------
__global__ __launch_bounds__(256) void sgemm_kernel(
    const float* __restrict__ A, const float* __restrict__ Bm,
    float* __restrict__ C, int M, int N, int K,
    const float* __restrict__ bias)
{
    constexpr int BM = 128, BN = 128, BK = 16;
    __shared__ float As[BK][BM + 4];
    __shared__ float Bs[BK][BN];

    const int tid = threadIdx.x;
    const int row0 = blockIdx.y * BM;
    const int col0 = blockIdx.x * BN;

    const int tx = tid & 15;   // 0..15 col tile
    const int ty = tid >> 4;   // 0..15 row tile

    float acc[8][8];
#pragma unroll
    for (int i = 0; i < 8; i++)
#pragma unroll
        for (int j = 0; j < 8; j++) acc[i][j] = 0.f;

    const int arow = tid >> 2;          // 0..63
    const int acol = (tid & 3) * 4;     // 0,4,8,12
    const int brow = tid >> 5;          // 0..7
    const int bcol = (tid & 31) * 4;    // 0..124

    for (int kk = 0; kk < K; kk += BK) {
        float4 a0 = *(const float4*)&A[(long)(row0 + arow) * K + kk + acol];
        float4 a1 = *(const float4*)&A[(long)(row0 + arow + 64) * K + kk + acol];
        As[acol + 0][arow] = a0.x; As[acol + 1][arow] = a0.y;
        As[acol + 2][arow] = a0.z; As[acol + 3][arow] = a0.w;
        As[acol + 0][arow + 64] = a1.x; As[acol + 1][arow + 64] = a1.y;
        As[acol + 2][arow + 64] = a1.z; As[acol + 3][arow + 64] = a1.w;

        float4 b0 = *(const float4*)&Bm[(long)(kk + brow) * N + col0 + bcol];
        float4 b1 = *(const float4*)&Bm[(long)(kk + brow + 8) * N + col0 + bcol];
        *(float4*)&Bs[brow][bcol] = b0;
        *(float4*)&Bs[brow + 8][bcol] = b1;
        __syncthreads();

#pragma unroll
        for (int k = 0; k < BK; k++) {
            float ar[8], br[8];
#pragma unroll
            for (int i = 0; i < 8; i++) ar[i] = As[k][ty * 8 + i];
#pragma unroll
            for (int j = 0; j < 8; j++) br[j] = Bs[k][tx * 8 + j];
#pragma unroll
            for (int i = 0; i < 8; i++)
#pragma unroll
                for (int j = 0; j < 8; j++) acc[i][j] += ar[i] * br[j];
        }
        __syncthreads();
    }

#pragma unroll
    for (int i = 0; i < 8; i++) {
        int r = row0 + ty * 8 + i;
#pragma unroll
        for (int j = 0; j < 8; j++) {
            int c = col0 + tx * 8 + j;
            float v = acc[i][j];
            if (bias) v += bias[c];
            C[(long)r * N + c] = v;
        }
    }
}

// ---------------------------------------------------------------------------
// Per-row kernel: neighbor top-32, rotary, qk, MLPs, softmaxes, outputs
// One block of 256 threads per (b,i) row. 4096 blocks.
// ---------------------------------------------------------------------------
__global__ __launch_bounds__(256) void attn_kernel(
    const float* __restrict__ coors,
    const float* __restrict__ wc1, const float* __restrict__ bc1,
    const float* __restrict__ wc2, const float* __restrict__ bc2,
    const float* __restrict__ wg,  const float* __restrict__ bg,
    const float* __restrict__ coors_scale,
    const float* __restrict__ coors_combine,
    float* __restrict__ out_coors)
{
    const int row = blockIdx.x;          // b*NPTS + i
    const int b = row / NPTS;
    const int i = row % NPTS;
    const int tid = threadIdx.x;
    const int lane = tid & 31;
    const int warp = tid >> 5;           // warp == head

    __shared__ float s_d2[NPTS];         // 8KB
    __shared__ float s_q[INNER];         // 2KB
    __shared__ float s_row[INNER];       // 2KB
    __shared__ float s_cos[KNB][32];     // 4KB
    __shared__ float s_sin[KNB][32];     // 4KB
    __shared__ int   s_idx[KNB];
    __shared__ float s_dist[KNB];
    __shared__ float s_qk[HEADS][KNB];
    __shared__ float s_attn[HEADS][KNB];
    __shared__ float s_cw[KNB][HEADS];
    __shared__ float s_gate[KNB][HEADS];
    __shared__ float s_wsum[KNB];
    __shared__ unsigned long long s_best;
    __shared__ float s_ci[3];

    const float* cb = coors + (long)b * NPTS * 3;
    if (tid < 3) s_ci[tid] = cb[i * 3 + tid];
    __syncthreads();
    const float cix = s_ci[0], ciy = s_ci[1], ciz = s_ci[2];

    // squared distances to all points
    for (int j = tid; j < NPTS; j += 256) {
        float dx = cix - cb[j * 3 + 0];
        float dy = ciy - cb[j * 3 + 1];
        float dz = ciz - cb[j * 3 + 2];
        s_d2[j] = dx * dx + dy * dy + dz * dz;
    }
    __syncthreads();

    // iterative argmin: 32 nearest (set only; order irrelevant downstream)
    for (int r = 0; r < KNB; r++) {
        if (tid == 0) s_best = 0xFFFFFFFFFFFFFFFFULL;
        __syncthreads();
        unsigned long long best = 0xFFFFFFFFFFFFFFFFULL;
        for (int j = tid; j < NPTS; j += 256) {
            unsigned long long key =
                ((unsigned long long)__float_as_uint(s_d2[j]) << 32) | (unsigned)j;
            best = min(best, key);
        }
        atomicMin(&s_best, best);
        __syncthreads();
        if (tid == 0) {
            unsigned long long kkey = s_best;
            int j = (int)(kkey & 0xFFFFFFFFu);
            float d2 = __uint_as_float((unsigned)(kkey >> 32));
            s_idx[r] = j;
            s_dist[r] = sqrtf(d2);
            s_d2[j] = __int_as_float(0x7F800000);  // +inf: exclude
        }
        __syncthreads();
    }

    // rotary cos/sin tables per neighbor: freqs[m] = min(dist*100,5000)*10000^(-2m/64)
    for (int idx = tid; idx < KNB * 32; idx += 256) {
        int r = idx >> 5, m = idx & 31;
        float t = fminf(s_dist[r] * 100.0f, 5000.0f);
        float invf = powf(10000.0f, -(float)(2 * m) / 64.0f);
        float f = t * invf;
        s_cos[r][m] = cosf(f);
        s_sin[r][m] = sinf(f);
    }

    // load q (rotary with zero freqs is identity)
    const long qbase = (long)row * QKVN;
    for (int d = tid; d < INNER; d += 256) s_q[d] = g_qkv[qbase + d];
    __syncthreads();

    // qk logits: warp w = head w, lane handles dims (lane, lane+32)
    const int hb = warp * DHEAD;
    for (int r = 0; r < KNB; r++) {
        const long kb = (long)(b * NPTS + s_idx[r]) * QKVN + INNER;
        for (int d = tid; d < INNER; d += 256) s_row[d] = g_qkv[kb + d];
        __syncthreads();
        float c1 = s_cos[r][lane >> 1],        sn1 = s_sin[r][lane >> 1];
        float c2 = s_cos[r][16 + (lane >> 1)], sn2 = s_sin[r][16 + (lane >> 1)];
        float k1 = s_row[hb + lane], k2 = s_row[hb + lane + 32];
        float rh1 = -s_row[hb + 2 * lane + 1];   // d<32: -x[2d+1]
        float rh2 =  s_row[hb + 2 * lane];       // d>=32: x[2(d-32)]
        float sum = s_q[hb + lane] * (k1 * c1 + rh1 * sn1)
                  + s_q[hb + lane + 32] * (k2 * c2 + rh2 * sn2);
#pragma unroll
        for (int off = 16; off; off >>= 1)
            sum += __shfl_down_sync(0xFFFFFFFFu, sum, off);
        if (lane == 0) s_qk[warp][r] = sum * 0.125f;  // SCALE = 64^-0.5
        __syncthreads();
    }

    // tiny MLPs per neighbor (thread j < 32 handles neighbor j)
    if (tid < KNB) {
        const int j = tid;
        float in[HEADS];
#pragma unroll
        for (int h = 0; h < HEADS; h++) in[h] = s_qk[h][j];
        float hid[16];
#pragma unroll
        for (int m = 0; m < 16; m++) {
            float a = bc1[m];
#pragma unroll
            for (int h = 0; h < HEADS; h++) a += in[h] * wc1[h * 16 + m];
            // gelu, tanh approximation (JAX default)
            float x3 = a * a * a;
            float tt = tanhf(0.7978845608028654f * (a + 0.044715f * x3));
            hid[m] = 0.5f * a * (1.0f + tt);
        }
#pragma unroll
        for (int h = 0; h < HEADS; h++) {
            float a = bc2[h];
#pragma unroll
            for (int m = 0; m < 16; m++) a += hid[m] * wc2[m * 8 + h];
            s_cw[j][h] = a;
            float g = bg[h];
#pragma unroll
            for (int hh = 0; hh < HEADS; hh++) g += in[hh] * wg[hh * 8 + h];
            s_gate[j][h] = tanhf(g);
        }
    }
    __syncthreads();

    // softmaxes over neighbors (thread h < 8 per head)
    if (tid < HEADS) {
        const int h = tid;
        float mx = -1e30f;
        for (int j = 0; j < KNB; j++) mx = fmaxf(mx, s_qk[h][j]);
        float ssum = 0.f;
        float e[KNB];
        for (int j = 0; j < KNB; j++) { e[j] = expf(s_qk[h][j] - mx); ssum += e[j]; }
        float inv = 1.0f / ssum;
        for (int j = 0; j < KNB; j++) s_attn[h][j] = e[j] * inv;

        mx = -1e30f;
        for (int j = 0; j < KNB; j++) mx = fmaxf(mx, s_cw[j][h]);
        ssum = 0.f;
        for (int j = 0; j < KNB; j++) { float v = expf(s_cw[j][h] - mx); s_cw[j][h] = v; ssum += v; }
        inv = 1.0f / ssum;
        for (int j = 0; j < KNB; j++) s_cw[j][h] *= inv;   // now coor_attn
    }
    __syncthreads();

    // per-neighbor combined coordinate weight
    if (tid < KNB) {
        float w = 0.f;
#pragma unroll
        for (int h = 0; h < HEADS; h++)
            w += s_cw[tid][h] * s_gate[tid][h] * coors_combine[h];
        s_wsum[tid] = w;
    }
    __syncthreads();

    // coords output
    if (tid < 3 && out_coors) {
        const int c = tid;
        const float cscale = coors_scale[0];
        float accv = 0.f;
        for (int j = 0; j < KNB; j++) {
            int jj = s_idx[j];
            float rel = s_ci[c] - cb[jj * 3 + c];
            float nrm = fmaxf(s_dist[j], 1e-8f);
            accv += (rel / nrm) * cscale * s_wsum[j];
        }
        out_coors[(long)row * 3 + c] = accv;
    }

    // feature output: out[h,d] = sum_j attn[h,j] * vrot[h,j,d]
    float acc1 = 0.f, acc2 = 0.f;
    for (int r = 0; r < KNB; r++) {
        const long vb = (long)(b * NPTS + s_idx[r]) * QKVN + 2 * INNER;
        for (int d = tid; d < INNER; d += 256) s_row[d] = g_qkv[vb + d];
        __syncthreads();
        float c1 = s_cos[r][lane >> 1],        sn1 = s_sin[r][lane >> 1];
        float c2 = s_cos[r][16 + (lane >> 1)], sn2 = s_sin[r][16 + (lane >> 1)];
        float v1 = s_row[hb + lane], v2 = s_row[hb + lane + 32];
        float rh1 = -s_row[hb + 2 * lane + 1];
        float rh2 =  s_row[hb + 2 * lane];
        float a = s_attn[warp][r];
        acc1 += a * (v1 * c1 + rh1 * sn1);
        acc2 += a * (v2 * c2 + rh2 * sn2);
        __syncthreads();
    }
    g_att[(long)row * INNER + hb + lane] = acc1;
    g_att[(long)row * INNER + hb + lane + 32] = acc2;
}

// ---------------------------------------------------------------------------
extern "C" void kernel_launch(void* const* d_in, const int* in_sizes, int n_in,
                              void* d_out, int out_size)
{
    const float* feats         = (const float*)d_in[0];
    const float* coors         = (const float*)d_in[1];
    const float* w_qkv         = (const float*)d_in[2];
    const float* w_out         = (const float*)d_in[3];
    const float* b_out         = (const float*)d_in[4];
    const float* wc1           = (const float*)d_in[5];
    const float* bc1           = (const float*)d_in[6];
    const float* wc2           = (const float*)d_in[7];
    const float* bc2           = (const float*)d_in[8];
    const float* wg            = (const float*)d_in[9];
    const float* bg            = (const float*)d_in[10];
    const float* coors_scale   = (const float*)d_in[11];
    const float* coors_combine = (const float*)d_in[12];

    float* out = (float*)d_out;
    float* out_coors = (out_size >= FEAT_OUT + ROWS * 3) ? out + FEAT_OUT : nullptr;

    float* qkv_ptr = nullptr;
    float* att_ptr = nullptr;
    cudaGetSymbolAddress((void**)&qkv_ptr, g_qkv);
    cudaGetSymbolAddress((void**)&att_ptr, g_att);

    // 1) qkv = feats @ w_qkv
    {
        dim3 grid(QKVN / 128, ROWS / 128);
        sgemm_kernel<<<grid, 256>>>(feats, w_qkv, qkv_ptr, ROWS, QKVN, DIMF, nullptr);
    }
    // 2) per-row neighbor attention
    {
        attn_kernel<<<ROWS, 256>>>(coors, wc1, bc1, wc2, bc2, wg, bg,
                                   coors_scale, coors_combine, out_coors);
    }
    // 3) out = att @ w_out + b_out
    {
        dim3 grid(DIMF / 128, ROWS / 128);
        sgemm_kernel<<<grid, 256>>>(att_ptr, w_out, out, ROWS, DIMF, INNER, b_out);
    }
}

// round 2
// speedup vs baseline: 1.2871x; 1.2871x over previous
#include <cuda_runtime.h>
#include <cuda_bf16.h>
#include <math.h>

// Problem constants
#define BATCH   2
#define NPTS    2048
#define HEADS   8
#define DHEAD   64
#define KNB     32
#define DIMF    512
#define INNER   512          // HEADS*DHEAD
#define QKVN    1536         // 3*INNER
#define ROWS    (BATCH*NPTS) // 4096
#define FEAT_OUT (ROWS*DIMF) // 2097152

#define INF_F __int_as_float(0x7F800000)

// Scratch (device globals: allocation-free per harness rules)
__device__ float g_qkv[ROWS * QKVN];   // 25.2 MB
__device__ float g_att[ROWS * INNER];  // 8.4 MB
__device__ int   g_nbr[ROWS * KNB];
__device__ float g_dst[ROWS * KNB];

// ---------------------------------------------------------------------------
// Register-blocked fp32 SGEMM: C[M,N] = A[M,K] @ B[K,N] (+ bias[N])
// ---------------------------------------------------------------------------
__global__ __launch_bounds__(256) void sgemm_kernel(
    const float* __restrict__ A, const float* __restrict__ Bm,
    float* __restrict__ C, int M, int N, int K,
    const float* __restrict__ bias)
{
    constexpr int BM = 128, BN = 128, BK = 16;
    __shared__ float As[BK][BM + 4];
    __shared__ float Bs[BK][BN];

    const int tid = threadIdx.x;
    const int row0 = blockIdx.y * BM;
    const int col0 = blockIdx.x * BN;

    const int tx = tid & 15;
    const int ty = tid >> 4;

    float acc[8][8];
#pragma unroll
    for (int i = 0; i < 8; i++)
#pragma unroll
        for (int j = 0; j < 8; j++) acc[i][j] = 0.f;

    const int arow = tid >> 2;
    const int acol = (tid & 3) * 4;
    const int brow = tid >> 5;
    const int bcol = (tid & 31) * 4;

    for (int kk = 0; kk < K; kk += BK) {
        float4 a0 = *(const float4*)&A[(long)(row0 + arow) * K + kk + acol];
        float4 a1 = *(const float4*)&A[(long)(row0 + arow + 64) * K + kk + acol];
        As[acol + 0][arow] = a0.x; As[acol + 1][arow] = a0.y;
        As[acol + 2][arow] = a0.z; As[acol + 3][arow] = a0.w;
        As[acol + 0][arow + 64] = a1.x; As[acol + 1][arow + 64] = a1.y;
        As[acol + 2][arow + 64] = a1.z; As[acol + 3][arow + 64] = a1.w;

        float4 b0 = *(const float4*)&Bm[(long)(kk + brow) * N + col0 + bcol];
        float4 b1 = *(const float4*)&Bm[(long)(kk + brow + 8) * N + col0 + bcol];
        *(float4*)&Bs[brow][bcol] = b0;
        *(float4*)&Bs[brow + 8][bcol] = b1;
        __syncthreads();

#pragma unroll
        for (int k = 0; k < BK; k++) {
            float ar[8], br[8];
#pragma unroll
            for (int i = 0; i < 8; i++) ar[i] = As[k][ty * 8 + i];
#pragma unroll
            for (int j = 0; j < 8; j++) br[j] = Bs[k][tx * 8 + j];
#pragma unroll
            for (int i = 0; i < 8; i++)
#pragma unroll
                for (int j = 0; j < 8; j++) acc[i][j] += ar[i] * br[j];
        }
        __syncthreads();
    }

#pragma unroll
    for (int i = 0; i < 8; i++) {
        int r = row0 + ty * 8 + i;
#pragma unroll
        for (int j = 0; j < 8; j++) {
            int c = col0 + tx * 8 + j;
            float v = acc[i][j];
            if (bias) v += bias[c];
            C[(long)r * N + c] = v;
        }
    }
}

// ---------------------------------------------------------------------------
// Selection kernel: 32 nearest neighbors per row via register-resident d².
// One barrier per selection round. Writes indices + distances to global.
// ---------------------------------------------------------------------------
__global__ __launch_bounds__(256) void select_kernel(
    const float* __restrict__ coors,
    int* __restrict__ nbr, float* __restrict__ dst)
{
    const int row = blockIdx.x;
    const int b = row / NPTS;
    const int i = row % NPTS;
    const int tid = threadIdx.x;

    __shared__ unsigned long long s_best[KNB];
    __shared__ float s_ci[3];

    if (tid < KNB) s_best[tid] = 0xFFFFFFFFFFFFFFFFULL;
    const float* cb = coors + (long)b * NPTS * 3;
    if (tid < 3) s_ci[tid] = cb[i * 3 + tid];
    __syncthreads();
    const float cix = s_ci[0], ciy = s_ci[1], ciz = s_ci[2];

    // 8 points per thread, coalesced: j = u*256 + tid
    float d2l[8];
#pragma unroll
    for (int u = 0; u < 8; u++) {
        int j = u * 256 + tid;
        float dx = cix - cb[j * 3 + 0];
        float dy = ciy - cb[j * 3 + 1];
        float dz = ciz - cb[j * 3 + 2];
        d2l[u] = dx * dx + dy * dy + dz * dz;
    }

    for (int r = 0; r < KNB; r++) {
        // local min over 8 register values
        float mn = d2l[0]; int mu = 0;
#pragma unroll
        for (int u = 1; u < 8; u++)
            if (d2l[u] < mn) { mn = d2l[u]; mu = u; }
        // packed key: (d2 bits << 32) | j  (d2 >= 0 so uint order == float order)
        unsigned long long key =
            ((unsigned long long)__float_as_uint(mn) << 32) | (unsigned)(mu * 256 + tid);
#pragma unroll
        for (int off = 16; off; off >>= 1) {
            unsigned long long o = __shfl_xor_sync(0xFFFFFFFFu, key, off);
            key = min(key, o);
        }
        if ((tid & 31) == 0) atomicMin(&s_best[r], key);
        __syncthreads();
        unsigned long long win = s_best[r];
        int wj = (int)(win & 0xFFFFFFFFu);
        if ((wj & 255) == tid) {
            int wu = wj >> 8;
#pragma unroll
            for (int u = 0; u < 8; u++)
                if (u == wu) d2l[u] = INF_F;   // static index
        }
        if (tid == 0) {
            nbr[(long)row * KNB + r] = wj;
            dst[(long)row * KNB + r] = sqrtf(__uint_as_float((unsigned)(win >> 32)));
        }
    }
}

// ---------------------------------------------------------------------------
// Attention kernel: warp = head; barrier-free qk / v loops with direct L2
// loads and shuffle-based rotate-half.
// ---------------------------------------------------------------------------
__global__ __launch_bounds__(256) void attn_kernel(
    const float* __restrict__ coors,
    const int* __restrict__ nbr, const float* __restrict__ dst,
    const float* __restrict__ wc1, const float* __restrict__ bc1,
    const float* __restrict__ wc2, const float* __restrict__ bc2,
    const float* __restrict__ wg,  const float* __restrict__ bg,
    const float* __restrict__ coors_scale,
    const float* __restrict__ coors_combine,
    float* __restrict__ out_coors)
{
    const int row = blockIdx.x;
    const int b = row / NPTS;
    const int i = row % NPTS;
    const int tid = threadIdx.x;
    const int lane = tid & 31;
    const int warp = tid >> 5;           // warp == head

    __shared__ int   s_idx[KNB];
    __shared__ float s_dist[KNB];
    __shared__ float s_cos[KNB][32];
    __shared__ float s_sin[KNB][32];
    __shared__ float s_qk[HEADS][KNB];
    __shared__ float s_attn[HEADS][KNB];
    __shared__ float s_cw[KNB][HEADS];
    __shared__ float s_gate[KNB][HEADS];
    __shared__ float s_wsum[KNB];
    __shared__ float s_ci[3];

    if (tid < KNB) {
        s_idx[tid]  = nbr[(long)row * KNB + tid];
        s_dist[tid] = dst[(long)row * KNB + tid];
    }
    const float* cb = coors + (long)b * NPTS * 3;
    if (tid < 3) s_ci[tid] = cb[i * 3 + tid];
    __syncthreads();

    // rotary cos/sin table: freqs[m] = min(dist*100,5000) * 10000^(-2m/64)
    for (int idx = tid; idx < KNB * 32; idx += 256) {
        int r = idx >> 5, m = idx & 31;
        float t = fminf(s_dist[r] * 100.0f, 5000.0f);
        float invf = powf(10000.0f, -(float)(2 * m) / 64.0f);
        float f = t * invf;
        float s, c;
        sincosf(f, &s, &c);
        s_cos[r][m] = c;
        s_sin[r][m] = s;
    }
    __syncthreads();

    const int hb = warp * DHEAD;
    const int fi1 = lane >> 1;           // freq index for d = lane
    const int fi2 = 16 + (lane >> 1);    // freq index for d = lane + 32
    const int m1 = (2 * lane + 1) & 31;  // shuffle src for rot-half of d = lane
    const int m2 = (2 * lane) & 31;      // shuffle src for rot-half of d = lane+32
    const bool lo = lane < 16;

    // q (rotary with zero freqs is identity)
    const long qbase = (long)row * QKVN + hb;
    const float q1 = g_qkv[qbase + lane];
    const float q2 = g_qkv[qbase + lane + 32];

    // qk logits (barrier-free, per-warp)
#pragma unroll 4
    for (int r = 0; r < KNB; r++) {
        const long kb = (long)(b * NPTS + s_idx[r]) * QKVN + INNER + hb;
        float k1 = __ldg(&g_qkv[kb + lane]);
        float k2 = __ldg(&g_qkv[kb + lane + 32]);
        float sa = __shfl_sync(0xFFFFFFFFu, k1, m1);
        float sb = __shfl_sync(0xFFFFFFFFu, k2, m1);
        float sc = __shfl_sync(0xFFFFFFFFu, k1, m2);
        float sd = __shfl_sync(0xFFFFFFFFu, k2, m2);
        float rh1 = -(lo ? sa : sb);     // -x[2d+1]
        float rh2 =  (lo ? sc : sd);     //  x[2(d-32)]
        float c1 = s_cos[r][fi1], sn1 = s_sin[r][fi1];
        float c2 = s_cos[r][fi2], sn2 = s_sin[r][fi2];
        float sum = q1 * (k1 * c1 + rh1 * sn1)
                  + q2 * (k2 * c2 + rh2 * sn2);
#pragma unroll
        for (int off = 16; off; off >>= 1)
            sum += __shfl_down_sync(0xFFFFFFFFu, sum, off);
        if (lane == 0) s_qk[warp][r] = sum * 0.125f;   // SCALE = 64^-0.5
    }
    __syncthreads();

    // tiny MLPs per neighbor (thread j < 32)
    if (tid < KNB) {
        const int j = tid;
        float in[HEADS];
#pragma unroll
        for (int h = 0; h < HEADS; h++) in[h] = s_qk[h][j];
        float hid[16];
#pragma unroll
        for (int m = 0; m < 16; m++) {
            float a = bc1[m];
#pragma unroll
            for (int h = 0; h < HEADS; h++) a += in[h] * wc1[h * 16 + m];
            float x3 = a * a * a;
            float tt = tanhf(0.7978845608028654f * (a + 0.044715f * x3));
            hid[m] = 0.5f * a * (1.0f + tt);
        }
#pragma unroll
        for (int h = 0; h < HEADS; h++) {
            float a = bc2[h];
#pragma unroll
            for (int m = 0; m < 16; m++) a += hid[m] * wc2[m * 8 + h];
            s_cw[j][h] = a;
            float g = bg[h];
#pragma unroll
            for (int hh = 0; hh < HEADS; hh++) g += in[hh] * wg[hh * 8 + h];
            s_gate[j][h] = tanhf(g);
        }
    }
    __syncthreads();

    // softmaxes over neighbors (thread h < 8)
    if (tid < HEADS) {
        const int h = tid;
        float mx = -1e30f;
        for (int j = 0; j < KNB; j++) mx = fmaxf(mx, s_qk[h][j]);
        float ssum = 0.f;
        float e[KNB];
        for (int j = 0; j < KNB; j++) { e[j] = expf(s_qk[h][j] - mx); ssum += e[j]; }
        float inv = 1.0f / ssum;
        for (int j = 0; j < KNB; j++) s_attn[h][j] = e[j] * inv;

        mx = -1e30f;
        for (int j = 0; j < KNB; j++) mx = fmaxf(mx, s_cw[j][h]);
        ssum = 0.f;
        for (int j = 0; j < KNB; j++) { float v = expf(s_cw[j][h] - mx); s_cw[j][h] = v; ssum += v; }
        inv = 1.0f / ssum;
        for (int j = 0; j < KNB; j++) s_cw[j][h] *= inv;   // now coor_attn
    }
    __syncthreads();

    // per-neighbor combined coordinate weight
    if (tid < KNB) {
        float w = 0.f;
#pragma unroll
        for (int h = 0; h < HEADS; h++)
            w += s_cw[tid][h] * s_gate[tid][h] * coors_combine[h];
        s_wsum[tid] = w;
    }
    __syncthreads();

    // coords output
    if (tid < 3 && out_coors) {
        const int c = tid;
        const float cscale = coors_scale[0];
        float accv = 0.f;
        for (int j = 0; j < KNB; j++) {
            int jj = s_idx[j];
            float rel = s_ci[c] - cb[jj * 3 + c];
            float nrm = fmaxf(s_dist[j], 1e-8f);
            accv += (rel / nrm) * cscale * s_wsum[j];
        }
        out_coors[(long)row * 3 + c] = accv;
    }

    // feature output (barrier-free, per-warp): out[h,d] = sum_j attn[h,j]*vrot[h,j,d]
    float acc1 = 0.f, acc2 = 0.f;
#pragma unroll 4
    for (int r = 0; r < KNB; r++) {
        const long vb = (long)(b * NPTS + s_idx[r]) * QKVN + 2 * INNER + hb;
        float v1 = __ldg(&g_qkv[vb + lane]);
        float v2 = __ldg(&g_qkv[vb + lane + 32]);
        float sa = __shfl_sync(0xFFFFFFFFu, v1, m1);
        float sb = __shfl_sync(0xFFFFFFFFu, v2, m1);
        float sc = __shfl_sync(0xFFFFFFFFu, v1, m2);
        float sd = __shfl_sync(0xFFFFFFFFu, v2, m2);
        float rh1 = -(lo ? sa : sb);
        float rh2 =  (lo ? sc : sd);
        float c1 = s_cos[r][fi1], sn1 = s_sin[r][fi1];
        float c2 = s_cos[r][fi2], sn2 = s_sin[r][fi2];
        float a = s_attn[warp][r];
        acc1 += a * (v1 * c1 + rh1 * sn1);
        acc2 += a * (v2 * c2 + rh2 * sn2);
    }
    g_att[(long)row * INNER + hb + lane] = acc1;
    g_att[(long)row * INNER + hb + lane + 32] = acc2;
}

// ---------------------------------------------------------------------------
extern "C" void kernel_launch(void* const* d_in, const int* in_sizes, int n_in,
                              void* d_out, int out_size)
{
    const float* feats         = (const float*)d_in[0];
    const float* coors         = (const float*)d_in[1];
    const float* w_qkv         = (const float*)d_in[2];
    const float* w_out         = (const float*)d_in[3];
    const float* b_out         = (const float*)d_in[4];
    const float* wc1           = (const float*)d_in[5];
    const float* bc1           = (const float*)d_in[6];
    const float* wc2           = (const float*)d_in[7];
    const float* bc2           = (const float*)d_in[8];
    const float* wg            = (const float*)d_in[9];
    const float* bg            = (const float*)d_in[10];
    const float* coors_scale   = (const float*)d_in[11];
    const float* coors_combine = (const float*)d_in[12];

    float* out = (float*)d_out;
    float* out_coors = (out_size >= FEAT_OUT + ROWS * 3) ? out + FEAT_OUT : nullptr;

    float* qkv_ptr = nullptr;
    float* att_ptr = nullptr;
    int*   nbr_ptr = nullptr;
    float* dst_ptr = nullptr;
    cudaGetSymbolAddress((void**)&qkv_ptr, g_qkv);
    cudaGetSymbolAddress((void**)&att_ptr, g_att);
    cudaGetSymbolAddress((void**)&nbr_ptr, g_nbr);
    cudaGetSymbolAddress((void**)&dst_ptr, g_dst);

    // 1) qkv = feats @ w_qkv
    {
        dim3 grid(QKVN / 128, ROWS / 128);
        sgemm_kernel<<<grid, 256>>>(feats, w_qkv, qkv_ptr, ROWS, QKVN, DIMF, nullptr);
    }
    // 2a) neighbor selection
    select_kernel<<<ROWS, 256>>>(coors, nbr_ptr, dst_ptr);
    // 2b) per-row neighbor attention
    attn_kernel<<<ROWS, 256>>>(coors, nbr_ptr, dst_ptr,
                               wc1, bc1, wc2, bc2, wg, bg,
                               coors_scale, coors_combine, out_coors);
    // 3) out = att @ w_out + b_out
    {
        dim3 grid(DIMF / 128, ROWS / 128);
        sgemm_kernel<<<grid, 256>>>(att_ptr, w_out, out, ROWS, DIMF, INNER, b_out);
    }
}

// round 3
// speedup vs baseline: 1.8146x; 1.4098x over previous
#include <cuda_runtime.h>
#include <cuda_bf16.h>
#include <math.h>
#include <stdint.h>

// Problem constants
#define BATCH   2
#define NPTS    2048
#define HEADS   8
#define DHEAD   64
#define KNB     32
#define DIMF    512
#define INNER   512          // HEADS*DHEAD
#define QKVN    1536         // 3*INNER
#define ROWS    (BATCH*NPTS) // 4096
#define FEAT_OUT (ROWS*DIMF) // 2097152

#define INF_F __int_as_float(0x7F800000)

// Scratch (device globals: allocation-free per harness rules)
__device__ float g_qkv[ROWS * QKVN];   // 25.2 MB
__device__ float g_att[ROWS * INNER];  // 8.4 MB
__device__ int   g_nbr[ROWS * KNB];
__device__ float g_dst[ROWS * KNB];

// ---------------------------------------------------------------------------
// TF32 tensor-core GEMM: C[M,N] = A[M,K] @ B[K,N] (+ bias[N])
// Block 128x128x32, 8 warps (2x4), warp tile 64x32 via mma.sync.m16n8k8
// Requires M%128==0, N%128==0, K%32==0.
// ---------------------------------------------------------------------------
__device__ __forceinline__ uint32_t f2tf32(float x) {
    uint32_t r;
    asm("cvt.rna.tf32.f32 %0, %1;" : "=r"(r) : "f"(x));
    return r;
}

__global__ __launch_bounds__(256) void tf32_gemm_kernel(
    const float* __restrict__ A, const float* __restrict__ Bm,
    float* __restrict__ C, int M, int N, int K,
    const float* __restrict__ bias)
{
    constexpr int BM = 128, BN = 128, BK = 32;
    constexpr int AP = BK + 4;   // 36: conflict-free for frag reads
    constexpr int BP = BN + 8;   // 136: conflict-free for frag reads
    __shared__ uint32_t As[BM * AP];
    __shared__ uint32_t Bs[BK * BP];

    const int tid = threadIdx.x;
    const int lane = tid & 31;
    const int wid = tid >> 5;
    const int wm = wid & 1;      // warp row: 0..1  (64 rows each)
    const int wn = wid >> 1;     // warp col: 0..3  (32 cols each)
    const int row0 = blockIdx.y * BM;
    const int col0 = blockIdx.x * BN;

    const int g  = lane >> 2;    // groupID 0..7
    const int tg = lane & 3;     // thread-in-group 0..3

    float acc[4][4][4];
#pragma unroll
    for (int i = 0; i < 4; i++)
#pragma unroll
        for (int j = 0; j < 4; j++)
#pragma unroll
            for (int r = 0; r < 4; r++) acc[i][j][r] = 0.f;

    // load mapping: A 128x32 (4 float4/thread), B 32x128 (4 float4/thread)
    const int ar = tid >> 3;           // 0..31 (+p*32)
    const int ac = (tid & 7) * 4;      // 0..28
    const int br = tid >> 5;           // 0..7  (+p*8)
    const int bc = (tid & 31) * 4;     // 0..124

    for (int kk = 0; kk < K; kk += BK) {
#pragma unroll
        for (int p = 0; p < 4; p++) {
            float4 av = *(const float4*)&A[(long)(row0 + ar + p * 32) * K + kk + ac];
            uint32_t* as = &As[(ar + p * 32) * AP + ac];
            as[0] = f2tf32(av.x); as[1] = f2tf32(av.y);
            as[2] = f2tf32(av.z); as[3] = f2tf32(av.w);
            float4 bv = *(const float4*)&Bm[(long)(kk + br + p * 8) * N + col0 + bc];
            uint32_t* bs = &Bs[(br + p * 8) * BP + bc];
            bs[0] = f2tf32(bv.x); bs[1] = f2tf32(bv.y);
            bs[2] = f2tf32(bv.z); bs[3] = f2tf32(bv.w);
        }
        __syncthreads();

#pragma unroll
        for (int ks = 0; ks < 4; ks++) {
            const int k0 = ks * 8;
            uint32_t a[4][4], b[4][2];
#pragma unroll
            for (int mi = 0; mi < 4; mi++) {
                const int r = wm * 64 + mi * 16 + g;
                a[mi][0] = As[r * AP + k0 + tg];
                a[mi][1] = As[(r + 8) * AP + k0 + tg];
                a[mi][2] = As[r * AP + k0 + tg + 4];
                a[mi][3] = As[(r + 8) * AP + k0 + tg + 4];
            }
#pragma unroll
            for (int nj = 0; nj < 4; nj++) {
                const int c = wn * 32 + nj * 8 + g;
                b[nj][0] = Bs[(k0 + tg) * BP + c];
                b[nj][1] = Bs[(k0 + tg + 4) * BP + c];
            }
#pragma unroll
            for (int mi = 0; mi < 4; mi++)
#pragma unroll
                for (int nj = 0; nj < 4; nj++) {
                    asm volatile(
                        "mma.sync.aligned.m16n8k8.row.col.f32.tf32.tf32.f32 "
                        "{%0,%1,%2,%3}, {%4,%5,%6,%7}, {%8,%9}, {%0,%1,%2,%3};"
                        : "+f"(acc[mi][nj][0]), "+f"(acc[mi][nj][1]),
                          "+f"(acc[mi][nj][2]), "+f"(acc[mi][nj][3])
                        : "r"(a[mi][0]), "r"(a[mi][1]), "r"(a[mi][2]), "r"(a[mi][3]),
                          "r"(b[nj][0]), "r"(b[nj][1]));
                }
        }
        __syncthreads();
    }

    // epilogue: c0,c1 at (row=g, col=2*tg, 2*tg+1); c2,c3 at row=g+8
#pragma unroll
    for (int mi = 0; mi < 4; mi++) {
        const int r = row0 + wm * 64 + mi * 16 + g;
#pragma unroll
        for (int nj = 0; nj < 4; nj++) {
            const int c = col0 + wn * 32 + nj * 8 + 2 * tg;
            float b0 = bias ? bias[c] : 0.f;
            float b1 = bias ? bias[c + 1] : 0.f;
            C[(long)r * N + c]           = acc[mi][nj][0] + b0;
            C[(long)r * N + c + 1]       = acc[mi][nj][1] + b1;
            C[(long)(r + 8) * N + c]     = acc[mi][nj][2] + b0;
            C[(long)(r + 8) * N + c + 1] = acc[mi][nj][3] + b1;
        }
    }
}

// ---------------------------------------------------------------------------
// Selection kernel: 32 nearest neighbors per row via register-resident d².
// ---------------------------------------------------------------------------
__global__ __launch_bounds__(256) void select_kernel(
    const float* __restrict__ coors,
    int* __restrict__ nbr, float* __restrict__ dst)
{
    const int row = blockIdx.x;
    const int b = row / NPTS;
    const int i = row % NPTS;
    const int tid = threadIdx.x;

    __shared__ unsigned long long s_best[KNB];
    __shared__ float s_ci[3];

    if (tid < KNB) s_best[tid] = 0xFFFFFFFFFFFFFFFFULL;
    const float* cb = coors + (long)b * NPTS * 3;
    if (tid < 3) s_ci[tid] = cb[i * 3 + tid];
    __syncthreads();
    const float cix = s_ci[0], ciy = s_ci[1], ciz = s_ci[2];

    float d2l[8];
#pragma unroll
    for (int u = 0; u < 8; u++) {
        int j = u * 256 + tid;
        float dx = cix - cb[j * 3 + 0];
        float dy = ciy - cb[j * 3 + 1];
        float dz = ciz - cb[j * 3 + 2];
        d2l[u] = dx * dx + dy * dy + dz * dz;
    }

    for (int r = 0; r < KNB; r++) {
        float mn = d2l[0]; int mu = 0;
#pragma unroll
        for (int u = 1; u < 8; u++)
            if (d2l[u] < mn) { mn = d2l[u]; mu = u; }
        unsigned long long key =
            ((unsigned long long)__float_as_uint(mn) << 32) | (unsigned)(mu * 256 + tid);
#pragma unroll
        for (int off = 16; off; off >>= 1) {
            unsigned long long o = __shfl_xor_sync(0xFFFFFFFFu, key, off);
            key = min(key, o);
        }
        if ((tid & 31) == 0) atomicMin(&s_best[r], key);
        __syncthreads();
        unsigned long long win = s_best[r];
        int wj = (int)(win & 0xFFFFFFFFu);
        if ((wj & 255) == tid) {
            int wu = wj >> 8;
#pragma unroll
            for (int u = 0; u < 8; u++)
                if (u == wu) d2l[u] = INF_F;
        }
        if (tid == 0) {
            nbr[(long)row * KNB + r] = wj;
            dst[(long)row * KNB + r] = sqrtf(__uint_as_float((unsigned)(win >> 32)));
        }
    }
}

// ---------------------------------------------------------------------------
// Attention kernel: warp = head; barrier-free qk / v loops with direct L2
// loads and shuffle-based rotate-half.
// ---------------------------------------------------------------------------
__global__ __launch_bounds__(256) void attn_kernel(
    const float* __restrict__ coors,
    const int* __restrict__ nbr, const float* __restrict__ dst,
    const float* __restrict__ wc1, const float* __restrict__ bc1,
    const float* __restrict__ wc2, const float* __restrict__ bc2,
    const float* __restrict__ wg,  const float* __restrict__ bg,
    const float* __restrict__ coors_scale,
    const float* __restrict__ coors_combine,
    float* __restrict__ out_coors)
{
    const int row = blockIdx.x;
    const int b = row / NPTS;
    const int i = row % NPTS;
    const int tid = threadIdx.x;
    const int lane = tid & 31;
    const int warp = tid >> 5;           // warp == head

    __shared__ int   s_idx[KNB];
    __shared__ float s_dist[KNB];
    __shared__ float s_cos[KNB][32];
    __shared__ float s_sin[KNB][32];
    __shared__ float s_qk[HEADS][KNB];
    __shared__ float s_attn[HEADS][KNB];
    __shared__ float s_cw[KNB][HEADS];
    __shared__ float s_gate[KNB][HEADS];
    __shared__ float s_wsum[KNB];
    __shared__ float s_ci[3];

    if (tid < KNB) {
        s_idx[tid]  = nbr[(long)row * KNB + tid];
        s_dist[tid] = dst[(long)row * KNB + tid];
    }
    const float* cb = coors + (long)b * NPTS * 3;
    if (tid < 3) s_ci[tid] = cb[i * 3 + tid];
    __syncthreads();

    // rotary cos/sin table: freqs[m] = min(dist*100,5000) * 10000^(-2m/64)
    // 10000^(-2m/64) = exp2f(-m * log2(10000)/32)
    for (int idx = tid; idx < KNB * 32; idx += 256) {
        int r = idx >> 5, m = idx & 31;
        float t = fminf(s_dist[r] * 100.0f, 5000.0f);
        float invf = exp2f((float)m * -0.41524099657040455f);
        float f = t * invf;
        float s, c;
        sincosf(f, &s, &c);
        s_cos[r][m] = c;
        s_sin[r][m] = s;
    }
    __syncthreads();

    const int hb = warp * DHEAD;
    const int fi1 = lane >> 1;
    const int fi2 = 16 + (lane >> 1);
    const int m1 = (2 * lane + 1) & 31;
    const int m2 = (2 * lane) & 31;
    const bool lo = lane < 16;

    const long qbase = (long)row * QKVN + hb;
    const float q1 = g_qkv[qbase + lane];
    const float q2 = g_qkv[qbase + lane + 32];

    // qk logits (barrier-free, per-warp)
#pragma unroll 4
    for (int r = 0; r < KNB; r++) {
        const long kb = (long)(b * NPTS + s_idx[r]) * QKVN + INNER + hb;
        float k1 = __ldg(&g_qkv[kb + lane]);
        float k2 = __ldg(&g_qkv[kb + lane + 32]);
        float sa = __shfl_sync(0xFFFFFFFFu, k1, m1);
        float sb = __shfl_sync(0xFFFFFFFFu, k2, m1);
        float sc = __shfl_sync(0xFFFFFFFFu, k1, m2);
        float sd = __shfl_sync(0xFFFFFFFFu, k2, m2);
        float rh1 = -(lo ? sa : sb);
        float rh2 =  (lo ? sc : sd);
        float c1 = s_cos[r][fi1], sn1 = s_sin[r][fi1];
        float c2 = s_cos[r][fi2], sn2 = s_sin[r][fi2];
        float sum = q1 * (k1 * c1 + rh1 * sn1)
                  + q2 * (k2 * c2 + rh2 * sn2);
#pragma unroll
        for (int off = 16; off; off >>= 1)
            sum += __shfl_down_sync(0xFFFFFFFFu, sum, off);
        if (lane == 0) s_qk[warp][r] = sum * 0.125f;
    }
    __syncthreads();

    // tiny MLPs per neighbor (thread j < 32)
    if (tid < KNB) {
        const int j = tid;
        float in[HEADS];
#pragma unroll
        for (int h = 0; h < HEADS; h++) in[h] = s_qk[h][j];
        float hid[16];
#pragma unroll
        for (int m = 0; m < 16; m++) {
            float a = bc1[m];
#pragma unroll
            for (int h = 0; h < HEADS; h++) a += in[h] * wc1[h * 16 + m];
            float x3 = a * a * a;
            float tt = tanhf(0.7978845608028654f * (a + 0.044715f * x3));
            hid[m] = 0.5f * a * (1.0f + tt);
        }
#pragma unroll
        for (int h = 0; h < HEADS; h++) {
            float a = bc2[h];
#pragma unroll
            for (int m = 0; m < 16; m++) a += hid[m] * wc2[m * 8 + h];
            s_cw[j][h] = a;
            float g = bg[h];
#pragma unroll
            for (int hh = 0; hh < HEADS; hh++) g += in[hh] * wg[hh * 8 + h];
            s_gate[j][h] = tanhf(g);
        }
    }
    __syncthreads();

    // softmaxes over neighbors (thread h < 8)
    if (tid < HEADS) {
        const int h = tid;
        float mx = -1e30f;
        for (int j = 0; j < KNB; j++) mx = fmaxf(mx, s_qk[h][j]);
        float ssum = 0.f;
        float e[KNB];
        for (int j = 0; j < KNB; j++) { e[j] = expf(s_qk[h][j] - mx); ssum += e[j]; }
        float inv = 1.0f / ssum;
        for (int j = 0; j < KNB; j++) s_attn[h][j] = e[j] * inv;

        mx = -1e30f;
        for (int j = 0; j < KNB; j++) mx = fmaxf(mx, s_cw[j][h]);
        ssum = 0.f;
        for (int j = 0; j < KNB; j++) { float v = expf(s_cw[j][h] - mx); s_cw[j][h] = v; ssum += v; }
        inv = 1.0f / ssum;
        for (int j = 0; j < KNB; j++) s_cw[j][h] *= inv;
    }
    __syncthreads();

    if (tid < KNB) {
        float w = 0.f;
#pragma unroll
        for (int h = 0; h < HEADS; h++)
            w += s_cw[tid][h] * s_gate[tid][h] * coors_combine[h];
        s_wsum[tid] = w;
    }
    __syncthreads();

    if (tid < 3 && out_coors) {
        const int c = tid;
        const float cscale = coors_scale[0];
        float accv = 0.f;
        for (int j = 0; j < KNB; j++) {
            int jj = s_idx[j];
            float rel = s_ci[c] - cb[jj * 3 + c];
            float nrm = fmaxf(s_dist[j], 1e-8f);
            accv += (rel / nrm) * cscale * s_wsum[j];
        }
        out_coors[(long)row * 3 + c] = accv;
    }

    // feature output (barrier-free, per-warp)
    float acc1 = 0.f, acc2 = 0.f;
#pragma unroll 4
    for (int r = 0; r < KNB; r++) {
        const long vb = (long)(b * NPTS + s_idx[r]) * QKVN + 2 * INNER + hb;
        float v1 = __ldg(&g_qkv[vb + lane]);
        float v2 = __ldg(&g_qkv[vb + lane + 32]);
        float sa = __shfl_sync(0xFFFFFFFFu, v1, m1);
        float sb = __shfl_sync(0xFFFFFFFFu, v2, m1);
        float sc = __shfl_sync(0xFFFFFFFFu, v1, m2);
        float sd = __shfl_sync(0xFFFFFFFFu, v2, m2);
        float rh1 = -(lo ? sa : sb);
        float rh2 =  (lo ? sc : sd);
        float c1 = s_cos[r][fi1], sn1 = s_sin[r][fi1];
        float c2 = s_cos[r][fi2], sn2 = s_sin[r][fi2];
        float a = s_attn[warp][r];
        acc1 += a * (v1 * c1 + rh1 * sn1);
        acc2 += a * (v2 * c2 + rh2 * sn2);
    }
    g_att[(long)row * INNER + hb + lane] = acc1;
    g_att[(long)row * INNER + hb + lane + 32] = acc2;
}

// ---------------------------------------------------------------------------
extern "C" void kernel_launch(void* const* d_in, const int* in_sizes, int n_in,
                              void* d_out, int out_size)
{
    const float* feats         = (const float*)d_in[0];
    const float* coors         = (const float*)d_in[1];
    const float* w_qkv         = (const float*)d_in[2];
    const float* w_out         = (const float*)d_in[3];
    const float* b_out         = (const float*)d_in[4];
    const float* wc1           = (const float*)d_in[5];
    const float* bc1           = (const float*)d_in[6];
    const float* wc2           = (const float*)d_in[7];
    const float* bc2           = (const float*)d_in[8];
    const float* wg            = (const float*)d_in[9];
    const float* bg            = (const float*)d_in[10];
    const float* coors_scale   = (const float*)d_in[11];
    const float* coors_combine = (const float*)d_in[12];

    float* out = (float*)d_out;
    float* out_coors = (out_size >= FEAT_OUT + ROWS * 3) ? out + FEAT_OUT : nullptr;

    float* qkv_ptr = nullptr;
    float* att_ptr = nullptr;
    int*   nbr_ptr = nullptr;
    float* dst_ptr = nullptr;
    cudaGetSymbolAddress((void**)&qkv_ptr, g_qkv);
    cudaGetSymbolAddress((void**)&att_ptr, g_att);
    cudaGetSymbolAddress((void**)&nbr_ptr, g_nbr);
    cudaGetSymbolAddress((void**)&dst_ptr, g_dst);

    // 1) qkv = feats @ w_qkv  (TF32 tensor cores)
    {
        dim3 grid(QKVN / 128, ROWS / 128);
        tf32_gemm_kernel<<<grid, 256>>>(feats, w_qkv, qkv_ptr, ROWS, QKVN, DIMF, nullptr);
    }
    // 2a) neighbor selection
    select_kernel<<<ROWS, 256>>>(coors, nbr_ptr, dst_ptr);
    // 2b) per-row neighbor attention
    attn_kernel<<<ROWS, 256>>>(coors, nbr_ptr, dst_ptr,
                               wc1, bc1, wc2, bc2, wg, bg,
                               coors_scale, coors_combine, out_coors);
    // 3) out = att @ w_out + b_out  (TF32 tensor cores)
    {
        dim3 grid(DIMF / 128, ROWS / 128);
        tf32_gemm_kernel<<<grid, 256>>>(att_ptr, w_out, out, ROWS, DIMF, INNER, b_out);
    }
}

// round 4
// speedup vs baseline: 2.2873x; 1.2605x over previous
#include <cuda_runtime.h>
#include <cuda_bf16.h>
#include <math.h>
#include <stdint.h>

// Problem constants
#define BATCH   2
#define NPTS    2048
#define HEADS   8
#define DHEAD   64
#define KNB     32
#define DIMF    512
#define INNER   512          // HEADS*DHEAD
#define QKVN    1536         // 3*INNER
#define ROWS    (BATCH*NPTS) // 4096
#define FEAT_OUT (ROWS*DIMF) // 2097152

#define INF_F __int_as_float(0x7F800000)

// Scratch (device globals: allocation-free per harness rules)
__device__ float g_qkv[ROWS * QKVN];   // 25.2 MB
__device__ float g_att[ROWS * INNER];  // 8.4 MB

// ---------------------------------------------------------------------------
// TF32 tensor-core GEMM with register-prefetch double buffering.
// C[M,N] = A[M,K] @ B[K,N] (+ bias[N]); block 128x128x32, 8 warps (2x4),
// warp tile 64x32 via mma.sync.m16n8k8.
// ---------------------------------------------------------------------------
__device__ __forceinline__ uint32_t f2tf32(float x) {
    uint32_t r;
    asm("cvt.rna.tf32.f32 %0, %1;" : "=r"(r) : "f"(x));
    return r;
}

__global__ __launch_bounds__(256) void tf32_gemm_kernel(
    const float* __restrict__ A, const float* __restrict__ Bm,
    float* __restrict__ C, int M, int N, int K,
    const float* __restrict__ bias)
{
    constexpr int BM = 128, BN = 128, BK = 32;
    constexpr int AP = BK + 4;   // 36
    constexpr int BP = BN + 8;   // 136
    __shared__ uint32_t As[BM * AP];
    __shared__ uint32_t Bs[BK * BP];

    const int tid = threadIdx.x;
    const int lane = tid & 31;
    const int wid = tid >> 5;
    const int wm = wid & 1;
    const int wn = wid >> 1;
    const int row0 = blockIdx.y * BM;
    const int col0 = blockIdx.x * BN;

    const int g  = lane >> 2;
    const int tg = lane & 3;

    float acc[4][4][4];
#pragma unroll
    for (int i = 0; i < 4; i++)
#pragma unroll
        for (int j = 0; j < 4; j++)
#pragma unroll
            for (int r = 0; r < 4; r++) acc[i][j][r] = 0.f;

    const int ar = tid >> 3;           // 0..31 (+p*32)
    const int ac = (tid & 7) * 4;      // 0..28
    const int br = tid >> 5;           // 0..7  (+p*8)
    const int bc = (tid & 31) * 4;     // 0..124

    float4 pa[4], pb[4];
#pragma unroll
    for (int p = 0; p < 4; p++) {
        pa[p] = *(const float4*)&A[(long)(row0 + ar + p * 32) * K + ac];
        pb[p] = *(const float4*)&Bm[(long)(br + p * 8) * N + col0 + bc];
    }

    for (int kk = 0; kk < K; kk += BK) {
#pragma unroll
        for (int p = 0; p < 4; p++) {
            uint32_t* as = &As[(ar + p * 32) * AP + ac];
            as[0] = f2tf32(pa[p].x); as[1] = f2tf32(pa[p].y);
            as[2] = f2tf32(pa[p].z); as[3] = f2tf32(pa[p].w);
            uint32_t* bs = &Bs[(br + p * 8) * BP + bc];
            bs[0] = f2tf32(pb[p].x); bs[1] = f2tf32(pb[p].y);
            bs[2] = f2tf32(pb[p].z); bs[3] = f2tf32(pb[p].w);
        }
        __syncthreads();

        // prefetch next tile (overlaps with MMA below)
        if (kk + BK < K) {
#pragma unroll
            for (int p = 0; p < 4; p++) {
                pa[p] = *(const float4*)&A[(long)(row0 + ar + p * 32) * K + kk + BK + ac];
                pb[p] = *(const float4*)&Bm[(long)(kk + BK + br + p * 8) * N + col0 + bc];
            }
        }

#pragma unroll
        for (int ks = 0; ks < 4; ks++) {
            const int k0 = ks * 8;
            uint32_t a[4][4], b[4][2];
#pragma unroll
            for (int mi = 0; mi < 4; mi++) {
                const int r = wm * 64 + mi * 16 + g;
                a[mi][0] = As[r * AP + k0 + tg];
                a[mi][1] = As[(r + 8) * AP + k0 + tg];
                a[mi][2] = As[r * AP + k0 + tg + 4];
                a[mi][3] = As[(r + 8) * AP + k0 + tg + 4];
            }
#pragma unroll
            for (int nj = 0; nj < 4; nj++) {
                const int c = wn * 32 + nj * 8 + g;
                b[nj][0] = Bs[(k0 + tg) * BP + c];
                b[nj][1] = Bs[(k0 + tg + 4) * BP + c];
            }
#pragma unroll
            for (int mi = 0; mi < 4; mi++)
#pragma unroll
                for (int nj = 0; nj < 4; nj++) {
                    asm volatile(
                        "mma.sync.aligned.m16n8k8.row.col.f32.tf32.tf32.f32 "
                        "{%0,%1,%2,%3}, {%4,%5,%6,%7}, {%8,%9}, {%0,%1,%2,%3};"
                        : "+f"(acc[mi][nj][0]), "+f"(acc[mi][nj][1]),
                          "+f"(acc[mi][nj][2]), "+f"(acc[mi][nj][3])
                        : "r"(a[mi][0]), "r"(a[mi][1]), "r"(a[mi][2]), "r"(a[mi][3]),
                          "r"(b[nj][0]), "r"(b[nj][1]));
                }
        }
        __syncthreads();
    }

#pragma unroll
    for (int mi = 0; mi < 4; mi++) {
        const int r = row0 + wm * 64 + mi * 16 + g;
#pragma unroll
        for (int nj = 0; nj < 4; nj++) {
            const int c = col0 + wn * 32 + nj * 8 + 2 * tg;
            float b0 = bias ? bias[c] : 0.f;
            float b1 = bias ? bias[c + 1] : 0.f;
            C[(long)r * N + c]           = acc[mi][nj][0] + b0;
            C[(long)r * N + c + 1]       = acc[mi][nj][1] + b1;
            C[(long)(r + 8) * N + c]     = acc[mi][nj][2] + b0;
            C[(long)(r + 8) * N + c + 1] = acc[mi][nj][3] + b1;
        }
    }
}

// ---------------------------------------------------------------------------
// Fused selection + attention kernel. One block (256 threads) per query row.
// Selection: per-warp top-32 (intra-warp, barrier-free) + single-warp merge.
// ---------------------------------------------------------------------------
__global__ __launch_bounds__(256) void sa_kernel(
    const float* __restrict__ coors,
    const float* __restrict__ wc1, const float* __restrict__ bc1,
    const float* __restrict__ wc2, const float* __restrict__ bc2,
    const float* __restrict__ wg,  const float* __restrict__ bg,
    const float* __restrict__ coors_scale,
    const float* __restrict__ coors_combine,
    float* __restrict__ out_coors)
{
    const int row = blockIdx.x;
    const int b = row >> 11;             // / NPTS
    const int i = row & (NPTS - 1);
    const int tid = threadIdx.x;
    const int lane = tid & 31;
    const int warp = tid >> 5;           // warp == head

    __shared__ unsigned long long s_cand[256];
    __shared__ int   s_idx[KNB];
    __shared__ float s_dist[KNB];
    __shared__ float s_cos[KNB][32];
    __shared__ float s_sin[KNB][32];
    __shared__ float s_qk[HEADS][KNB];
    __shared__ float s_attn[HEADS][KNB];
    __shared__ float s_cw[KNB][HEADS];
    __shared__ float s_gate[KNB][HEADS];
    __shared__ float s_hid[KNB][16];
    __shared__ float s_ci[3];

    const float* cb = coors + (long)b * NPTS * 3;
    if (tid < 3) s_ci[tid] = cb[i * 3 + tid];
    __syncthreads();
    const float cix = s_ci[0], ciy = s_ci[1], ciz = s_ci[2];

    // q prefetch (rotary with zero freqs is identity)
    const int hb = warp * DHEAD;
    const long qbase = (long)row * QKVN + hb;
    const float q1 = g_qkv[qbase + lane];
    const float q2 = g_qkv[qbase + lane + 32];

    // squared distances: warp w owns points [w*256, w*256+256)
    float d2l[8];
#pragma unroll
    for (int u = 0; u < 8; u++) {
        int j = warp * 256 + u * 32 + lane;
        float dx = cix - cb[j * 3 + 0];
        float dy = ciy - cb[j * 3 + 1];
        float dz = ciz - cb[j * 3 + 2];
        d2l[u] = dx * dx + dy * dy + dz * dz;
    }

    // Phase A: per-warp top-32 (no barriers, no atomics)
    for (int r = 0; r < KNB; r++) {
        float mn = d2l[0]; int mu = 0;
#pragma unroll
        for (int u = 1; u < 8; u++)
            if (d2l[u] < mn) { mn = d2l[u]; mu = u; }
        unsigned long long key =
            ((unsigned long long)__float_as_uint(mn) << 32)
            | (unsigned)(warp * 256 + mu * 32 + lane);
#pragma unroll
        for (int off = 16; off; off >>= 1) {
            unsigned long long o = __shfl_xor_sync(0xFFFFFFFFu, key, off);
            key = min(key, o);
        }
        int wj = (int)(key & 0xFFFFFFFFu);
        if (lane == (wj & 31)) {
            int wu = (wj >> 5) & 7;
#pragma unroll
            for (int u = 0; u < 8; u++)
                if (u == wu) d2l[u] = INF_F;
        }
        if (lane == 0) s_cand[warp * KNB + r] = key;
    }
    __syncthreads();

    // Phase B: warp 0 merges 256 candidates -> global top-32
    if (warp == 0) {
        unsigned long long c[8];
#pragma unroll
        for (int u = 0; u < 8; u++) c[u] = s_cand[u * 32 + lane];
        for (int r = 0; r < KNB; r++) {
            unsigned long long key = c[0];
#pragma unroll
            for (int u = 1; u < 8; u++) key = min(key, c[u]);
#pragma unroll
            for (int off = 16; off; off >>= 1) {
                unsigned long long o = __shfl_xor_sync(0xFFFFFFFFu, key, off);
                key = min(key, o);
            }
#pragma unroll
            for (int u = 0; u < 8; u++)
                if (c[u] == key) c[u] = 0xFFFFFFFFFFFFFFFFULL;
            if (lane == 0) {
                s_idx[r]  = (int)(key & 0xFFFFFFFFu);
                s_dist[r] = sqrtf(__uint_as_float((unsigned)(key >> 32)));
            }
        }
    }
    __syncthreads();

    // rotary cos/sin: freqs[m] = min(dist*100,5000) * 10000^(-2m/64)
    for (int idx = tid; idx < KNB * 32; idx += 256) {
        int r = idx >> 5, m = idx & 31;
        float t = fminf(s_dist[r] * 100.0f, 5000.0f);
        float invf = exp2f((float)m * -0.41524099657040455f);
        float f = t * invf;
        float s, c;
        sincosf(f, &s, &c);
        s_cos[r][m] = c;
        s_sin[r][m] = s;
    }
    __syncthreads();

    const int fi1 = lane >> 1;
    const int fi2 = 16 + (lane >> 1);
    const int m1 = (2 * lane + 1) & 31;
    const int m2 = (2 * lane) & 31;
    const bool lo = lane < 16;

    // qk logits (barrier-free, per-warp)
#pragma unroll 4
    for (int r = 0; r < KNB; r++) {
        const long kb = (long)(b * NPTS + s_idx[r]) * QKVN + INNER + hb;
        float k1 = __ldg(&g_qkv[kb + lane]);
        float k2 = __ldg(&g_qkv[kb + lane + 32]);
        float sa = __shfl_sync(0xFFFFFFFFu, k1, m1);
        float sb = __shfl_sync(0xFFFFFFFFu, k2, m1);
        float sc = __shfl_sync(0xFFFFFFFFu, k1, m2);
        float sd = __shfl_sync(0xFFFFFFFFu, k2, m2);
        float rh1 = -(lo ? sa : sb);
        float rh2 =  (lo ? sc : sd);
        float c1 = s_cos[r][fi1], sn1 = s_sin[r][fi1];
        float c2 = s_cos[r][fi2], sn2 = s_sin[r][fi2];
        float sum = q1 * (k1 * c1 + rh1 * sn1)
                  + q2 * (k2 * c2 + rh2 * sn2);
#pragma unroll
        for (int off = 16; off; off >>= 1)
            sum += __shfl_down_sync(0xFFFFFFFFu, sum, off);
        if (lane == 0) s_qk[warp][r] = sum * 0.125f;
    }
    __syncthreads();

    // tiny MLPs, parallel over (neighbor j, head/slot s): tid = j*8 + s
    {
        const int j = tid >> 3;
        const int s = tid & 7;
        float in[HEADS];
#pragma unroll
        for (int h = 0; h < HEADS; h++) in[h] = s_qk[h][j];
        // layer 1: this thread computes hidden units 2s, 2s+1
#pragma unroll
        for (int t = 0; t < 2; t++) {
            const int m = 2 * s + t;
            float a = bc1[m];
#pragma unroll
            for (int h = 0; h < HEADS; h++) a += in[h] * wc1[h * 16 + m];
            float x3 = a * a * a;
            float tt = tanhf(0.7978845608028654f * (a + 0.044715f * x3));
            s_hid[j][m] = 0.5f * a * (1.0f + tt);
        }
        __syncwarp();
        // layer 2 + gate: this thread computes head h = s for neighbor j
        float a = bc2[s];
#pragma unroll
        for (int m = 0; m < 16; m++) a += s_hid[j][m] * wc2[m * 8 + s];
        s_cw[j][s] = a;
        float gg = bg[s];
#pragma unroll
        for (int h = 0; h < HEADS; h++) gg += in[h] * wg[h * 8 + s];
        s_gate[j][s] = tanhf(gg);
    }
    __syncthreads();

    // softmaxes: warp h handles head h, lane j handles neighbor j
    {
        const int h = warp;
        // feature attention softmax over j
        float v = s_qk[h][lane];
        float mx = v;
#pragma unroll
        for (int off = 16; off; off >>= 1)
            mx = fmaxf(mx, __shfl_xor_sync(0xFFFFFFFFu, mx, off));
        float e = expf(v - mx);
        float ssum = e;
#pragma unroll
        for (int off = 16; off; off >>= 1)
            ssum += __shfl_xor_sync(0xFFFFFFFFu, ssum, off);
        s_attn[h][lane] = e / ssum;
        // coordinate-weight softmax over j
        float w = s_cw[lane][h];
        float mx2 = w;
#pragma unroll
        for (int off = 16; off; off >>= 1)
            mx2 = fmaxf(mx2, __shfl_xor_sync(0xFFFFFFFFu, mx2, off));
        float e2 = expf(w - mx2);
        float ssum2 = e2;
#pragma unroll
        for (int off = 16; off; off >>= 1)
            ssum2 += __shfl_xor_sync(0xFFFFFFFFu, ssum2, off);
        s_cw[lane][h] = e2 / ssum2;
    }
    __syncthreads();

    // coordinates output: warp 0, lane j = neighbor j
    if (warp == 0 && out_coors) {
        float w = 0.f;
#pragma unroll
        for (int h = 0; h < HEADS; h++)
            w += s_cw[lane][h] * s_gate[lane][h] * coors_combine[h];
        const int jj = s_idx[lane];
        const float nrm = fmaxf(s_dist[lane], 1e-8f);
        const float cscale = coors_scale[0] * w / nrm;
        float vx = (cix - cb[jj * 3 + 0]) * cscale;
        float vy = (ciy - cb[jj * 3 + 1]) * cscale;
        float vz = (ciz - cb[jj * 3 + 2]) * cscale;
#pragma unroll
        for (int off = 16; off; off >>= 1) {
            vx += __shfl_xor_sync(0xFFFFFFFFu, vx, off);
            vy += __shfl_xor_sync(0xFFFFFFFFu, vy, off);
            vz += __shfl_xor_sync(0xFFFFFFFFu, vz, off);
        }
        if (lane == 0) {
            out_coors[(long)row * 3 + 0] = vx;
            out_coors[(long)row * 3 + 1] = vy;
            out_coors[(long)row * 3 + 2] = vz;
        }
    }

    // feature output (barrier-free, per-warp)
    float acc1 = 0.f, acc2 = 0.f;
#pragma unroll 4
    for (int r = 0; r < KNB; r++) {
        const long vb = (long)(b * NPTS + s_idx[r]) * QKVN + 2 * INNER + hb;
        float v1 = __ldg(&g_qkv[vb + lane]);
        float v2 = __ldg(&g_qkv[vb + lane + 32]);
        float sa = __shfl_sync(0xFFFFFFFFu, v1, m1);
        float sb = __shfl_sync(0xFFFFFFFFu, v2, m1);
        float sc = __shfl_sync(0xFFFFFFFFu, v1, m2);
        float sd = __shfl_sync(0xFFFFFFFFu, v2, m2);
        float rh1 = -(lo ? sa : sb);
        float rh2 =  (lo ? sc : sd);
        float c1 = s_cos[r][fi1], sn1 = s_sin[r][fi1];
        float c2 = s_cos[r][fi2], sn2 = s_sin[r][fi2];
        float a = s_attn[warp][r];
        acc1 += a * (v1 * c1 + rh1 * sn1);
        acc2 += a * (v2 * c2 + rh2 * sn2);
    }
    g_att[(long)row * INNER + hb + lane] = acc1;
    g_att[(long)row * INNER + hb + lane + 32] = acc2;
}

// ---------------------------------------------------------------------------
extern "C" void kernel_launch(void* const* d_in, const int* in_sizes, int n_in,
                              void* d_out, int out_size)
{
    const float* feats         = (const float*)d_in[0];
    const float* coors         = (const float*)d_in[1];
    const float* w_qkv         = (const float*)d_in[2];
    const float* w_out         = (const float*)d_in[3];
    const float* b_out         = (const float*)d_in[4];
    const float* wc1           = (const float*)d_in[5];
    const float* bc1           = (const float*)d_in[6];
    const float* wc2           = (const float*)d_in[7];
    const float* bc2           = (const float*)d_in[8];
    const float* wg            = (const float*)d_in[9];
    const float* bg            = (const float*)d_in[10];
    const float* coors_scale   = (const float*)d_in[11];
    const float* coors_combine = (const float*)d_in[12];

    float* out = (float*)d_out;
    float* out_coors = (out_size >= FEAT_OUT + ROWS * 3) ? out + FEAT_OUT : nullptr;

    float* qkv_ptr = nullptr;
    float* att_ptr = nullptr;
    cudaGetSymbolAddress((void**)&qkv_ptr, g_qkv);
    cudaGetSymbolAddress((void**)&att_ptr, g_att);

    // 1) qkv = feats @ w_qkv  (TF32 tensor cores)
    {
        dim3 grid(QKVN / 128, ROWS / 128);
        tf32_gemm_kernel<<<grid, 256>>>(feats, w_qkv, qkv_ptr, ROWS, QKVN, DIMF, nullptr);
    }
    // 2) fused neighbor selection + attention
    sa_kernel<<<ROWS, 256>>>(coors, wc1, bc1, wc2, bc2, wg, bg,
                             coors_scale, coors_combine, out_coors);
    // 3) out = att @ w_out + b_out  (TF32 tensor cores)
    {
        dim3 grid(DIMF / 128, ROWS / 128);
        tf32_gemm_kernel<<<grid, 256>>>(att_ptr, w_out, out, ROWS, DIMF, INNER, b_out);
    }
}